// round 11
// baseline (speedup 1.0000x reference)
#include <cuda_runtime.h>
#include <cuda_bf16.h>
#include <cstdint>
#include <cstring>

#define DIM 64
#define NODES_MAX 100000
#define EDGES_MAX 1600000

// Allocation-free scratch (__device__ globals).
__device__ int g_count[NODES_MAX];   // node degree (persists)
__device__ int g_start[NODES_MAX];   // CSR bucket starts
__device__ int g_csr[EDGES_MAX];     // src per bucketed edge
__device__ int g_rank[EDGES_MAX];    // edge rank within bucket
__device__ int g_cursor;             // global bucket allocator

// ===========================================================================
// 1. zero degree counters + global cursor
// ===========================================================================
__global__ void zero_count_kernel(int N) {
    int i = blockIdx.x * blockDim.x + threadIdx.x;
    if (i < N) g_count[i] = 0;
    if (i == 0) g_cursor = 0;
}

// ===========================================================================
// 2. histogram of dst; the returned old value IS the edge's bucket rank
// ===========================================================================
__global__ void hist_rank_kernel(const int* __restrict__ dst, int E) {
    int i = blockIdx.x * blockDim.x + threadIdx.x;
    if (i < E) g_rank[i] = atomicAdd(&g_count[dst[i]], 1);
}

// ===========================================================================
// 3. one-pass scan: per-block local exclusive scan + atomic block base.
// Buckets not in node order (fine: gather uses start[n] + degree[n]).
// ===========================================================================
__global__ __launch_bounds__(1024) void scan_kernel(int N) {
    __shared__ int sd[1024];
    __shared__ int base_sh;
    int t = threadIdx.x;
    int i = blockIdx.x * 1024 + t;
    int v = (i < N) ? g_count[i] : 0;
    sd[t] = v;
    __syncthreads();
    #pragma unroll
    for (int off = 1; off < 1024; off <<= 1) {
        int u = (t >= off) ? sd[t - off] : 0;
        __syncthreads();
        sd[t] += u;
        __syncthreads();
    }
    if (t == 1023) base_sh = atomicAdd(&g_cursor, sd[1023]);
    __syncthreads();
    if (i < N) g_start[i] = base_sh + sd[t] - v;
}

// ===========================================================================
// 4. atomic-free fill: pos = start[dst] + rank
// ===========================================================================
__global__ void fill_kernel(const int* __restrict__ src,
                            const int* __restrict__ dst, int E) {
    int i = blockIdx.x * blockDim.x + threadIdx.x;
    if (i < E) {
        g_csr[g_start[dst[i]] + g_rank[i]] = src[i];
    }
}

// ===========================================================================
// 5. FUSED gather + tensor-core MLP.
// Block = 128 nodes, 256 threads = 8 warps. Phase 1: warp w pull-gathers
// rows w*16..w*16+15 (16 lanes x 2 slots, 4 loads in flight) and writes
// h = x + sum directly into split-bf16 SMEM A tiles. Phase 2: mma.sync
// m16n8k16 bf16 with split precision (D = AhBh + AhBl + AlBh, err ~2^-17);
// layer-2 A fragments built in registers from layer-1 accumulators.
// ===========================================================================
__device__ __forceinline__ uint32_t smem_u32(const void* p) {
    uint32_t a;
    asm("{ .reg .u64 t; cvta.to.shared.u64 t, %1; cvt.u32.u64 %0, t; }"
        : "=r"(a) : "l"(p));
    return a;
}

__device__ __forceinline__ void ldm4(uint32_t* f, uint32_t addr) {
    asm volatile("ldmatrix.sync.aligned.m8n8.x4.shared.b16 {%0,%1,%2,%3}, [%4];"
                 : "=r"(f[0]), "=r"(f[1]), "=r"(f[2]), "=r"(f[3]) : "r"(addr));
}

__device__ __forceinline__ void mma16816(float* d, const uint32_t* a,
                                         uint32_t b0, uint32_t b1) {
    asm volatile(
        "mma.sync.aligned.m16n8k16.row.col.f32.bf16.bf16.f32 "
        "{%0,%1,%2,%3}, {%4,%5,%6,%7}, {%8,%9}, {%0,%1,%2,%3};"
        : "+f"(d[0]), "+f"(d[1]), "+f"(d[2]), "+f"(d[3])
        : "r"(a[0]), "r"(a[1]), "r"(a[2]), "r"(a[3]), "r"(b0), "r"(b1));
}

__device__ __forceinline__ uint32_t pack_bf(__nv_bfloat16 a, __nv_bfloat16 b) {
    __nv_bfloat162 t;
    t.x = a; t.y = b;
    uint32_t r;
    memcpy(&r, &t, 4);
    return r;
}

__device__ __forceinline__ void split2(float a, float b,
                                       uint32_t& hi, uint32_t& lo) {
    __nv_bfloat16 ah = __float2bfloat16_rn(a);
    __nv_bfloat16 bh = __float2bfloat16_rn(b);
    hi = pack_bf(ah, bh);
    lo = pack_bf(__float2bfloat16_rn(a - __bfloat162float(ah)),
                 __float2bfloat16_rn(b - __bfloat162float(bh)));
}

#define STRIDE 144
#define A_HI_OFF 0
#define A_LO_OFF 18432
#define B1H_OFF  36864
#define B1L_OFF  46080
#define B2H_OFF  55296
#define B2L_OFF  64512
#define MLP_SMEM 73728

__global__ __launch_bounds__(256) void fused_kernel(const float* __restrict__ x,
                                                    const float* __restrict__ W1,
                                                    const float* __restrict__ b1,
                                                    const float* __restrict__ W2,
                                                    const float* __restrict__ b2,
                                                    float* __restrict__ out,
                                                    int N) {
    extern __shared__ char sm[];
    const uint32_t sbase = smem_u32(sm);
    const int tid  = threadIdx.x;
    const int node0 = blockIdx.x * 128;

    const int w    = tid >> 5;
    const int lane = tid & 31;
    const int c    = lane & 15;   // float4 chunk (gather)
    const int slot = lane >> 4;   // 0/1 (gather)

    // ---- Phase 1a: weight staging (overlaps gather) ----
    for (int i = tid; i < 1024; i += 256) {
        int k  = i >> 4;
        int n0 = (i & 15) * 4;
        float4 w1v = ((const float4*)W1)[i];
        float4 w2v = ((const float4*)W2)[i];
        #pragma unroll
        for (int j = 0; j < 4; j++) {
            uint32_t off = (uint32_t)(n0 + j) * STRIDE + (uint32_t)k * 2;
            float v1 = (&w1v.x)[j];
            __nv_bfloat16 h1b = __float2bfloat16_rn(v1);
            *(__nv_bfloat16*)(sm + B1H_OFF + off) = h1b;
            *(__nv_bfloat16*)(sm + B1L_OFF + off) =
                __float2bfloat16_rn(v1 - __bfloat162float(h1b));
            float v2 = (&w2v.x)[j];
            __nv_bfloat16 h2b = __float2bfloat16_rn(v2);
            *(__nv_bfloat16*)(sm + B2H_OFF + off) = h2b;
            *(__nv_bfloat16*)(sm + B2L_OFF + off) =
                __float2bfloat16_rn(v2 - __bfloat162float(h2b));
        }
    }

    // ---- Phase 1b: pull-gather 16 rows per warp -> split-bf16 A tiles ----
    const float4* x4 = (const float4*)x;
    #pragma unroll 1
    for (int i = 0; i < 16; i++) {
        const int m = w * 16 + i;
        const int node = node0 + m;
        float4 a = make_float4(0.f, 0.f, 0.f, 0.f);
        if (node < N) {
            const int s = __ldg(&g_start[node]);
            const int e = s + __ldg(&g_count[node]);
            int j = s + slot;
            for (; j + 2 < e; j += 4) {
                int nb0 = __ldg(&g_csr[j]);
                int nb1 = __ldg(&g_csr[j + 2]);
                float4 v0 = __ldg(&x4[(size_t)nb0 * 16 + c]);
                float4 v1 = __ldg(&x4[(size_t)nb1 * 16 + c]);
                a.x += v0.x + v1.x;
                a.y += v0.y + v1.y;
                a.z += v0.z + v1.z;
                a.w += v0.w + v1.w;
            }
            if (j < e) {
                int nb = __ldg(&g_csr[j]);
                float4 v = __ldg(&x4[(size_t)nb * 16 + c]);
                a.x += v.x; a.y += v.y; a.z += v.z; a.w += v.w;
            }
        }
        a.x += __shfl_xor_sync(0xffffffffu, a.x, 16);
        a.y += __shfl_xor_sync(0xffffffffu, a.y, 16);
        a.z += __shfl_xor_sync(0xffffffffu, a.z, 16);
        a.w += __shfl_xor_sync(0xffffffffu, a.w, 16);

        if (slot == 0) {
            if (node < N) {
                float4 xv = __ldg(&x4[(size_t)node * 16 + c]);
                a.x += xv.x; a.y += xv.y; a.z += xv.z; a.w += xv.w;
            }
            uint32_t h0, l0, h1, l1;
            split2(a.x, a.y, h0, l0);
            split2(a.z, a.w, h1, l1);
            uint32_t off = (uint32_t)m * STRIDE + (uint32_t)c * 8;
            *(uint2*)(sm + A_HI_OFF + off) = make_uint2(h0, h1);
            *(uint2*)(sm + A_LO_OFF + off) = make_uint2(l0, l1);
        }
    }
    __syncthreads();

    // ---- Phase 2: tensor-core MLP ----
    const int g = lane >> 2;
    const int t = lane & 3;
    const int q = lane >> 3;
    const int r = lane & 7;

    const uint32_t aoff = (uint32_t)(w * 16 + (q & 1) * 8 + r) * STRIDE
                        + (uint32_t)(q >> 1) * 16;
    const uint32_t boff0 = (uint32_t)((q >> 1) * 8 + r) * STRIDE
                         + (uint32_t)(q & 1) * 16;

    float acc1[8][4];
    #pragma unroll
    for (int n = 0; n < 8; n++)
        #pragma unroll
        for (int j = 0; j < 4; j++) acc1[n][j] = 0.f;

    #pragma unroll
    for (int kk = 0; kk < 4; kk++) {
        uint32_t ah[4], al[4];
        ldm4(ah, sbase + A_HI_OFF + aoff + kk * 32);
        ldm4(al, sbase + A_LO_OFF + aoff + kk * 32);
        #pragma unroll
        for (int p = 0; p < 4; p++) {
            uint32_t bo = boff0 + (uint32_t)p * 16 * STRIDE + kk * 32;
            uint32_t bh[4], bl[4];
            ldm4(bh, sbase + B1H_OFF + bo);
            ldm4(bl, sbase + B1L_OFF + bo);
            mma16816(acc1[2 * p],     ah, bh[0], bh[1]);
            mma16816(acc1[2 * p],     ah, bl[0], bl[1]);
            mma16816(acc1[2 * p],     al, bh[0], bh[1]);
            mma16816(acc1[2 * p + 1], ah, bh[2], bh[3]);
            mma16816(acc1[2 * p + 1], ah, bl[2], bl[3]);
            mma16816(acc1[2 * p + 1], al, bh[2], bh[3]);
        }
    }

    float acc2[8][4];
    #pragma unroll
    for (int n = 0; n < 8; n++)
        #pragma unroll
        for (int j = 0; j < 4; j++) acc2[n][j] = 0.f;

    #pragma unroll
    for (int kk = 0; kk < 4; kk++) {
        uint32_t ah[4], al[4];
        {
            int nt = 2 * kk;
            float bb0 = __ldg(&b1[nt * 8 + 2 * t]);
            float bb1 = __ldg(&b1[nt * 8 + 2 * t + 1]);
            split2(fmaxf(acc1[nt][0] + bb0, 0.f),
                   fmaxf(acc1[nt][1] + bb1, 0.f), ah[0], al[0]);
            split2(fmaxf(acc1[nt][2] + bb0, 0.f),
                   fmaxf(acc1[nt][3] + bb1, 0.f), ah[1], al[1]);
            nt = 2 * kk + 1;
            bb0 = __ldg(&b1[nt * 8 + 2 * t]);
            bb1 = __ldg(&b1[nt * 8 + 2 * t + 1]);
            split2(fmaxf(acc1[nt][0] + bb0, 0.f),
                   fmaxf(acc1[nt][1] + bb1, 0.f), ah[2], al[2]);
            split2(fmaxf(acc1[nt][2] + bb0, 0.f),
                   fmaxf(acc1[nt][3] + bb1, 0.f), ah[3], al[3]);
        }
        #pragma unroll
        for (int p = 0; p < 4; p++) {
            uint32_t bo = boff0 + (uint32_t)p * 16 * STRIDE + kk * 32;
            uint32_t bh[4], bl[4];
            ldm4(bh, sbase + B2H_OFF + bo);
            ldm4(bl, sbase + B2L_OFF + bo);
            mma16816(acc2[2 * p],     ah, bh[0], bh[1]);
            mma16816(acc2[2 * p],     ah, bl[0], bl[1]);
            mma16816(acc2[2 * p],     al, bh[0], bh[1]);
            mma16816(acc2[2 * p + 1], ah, bh[2], bh[3]);
            mma16816(acc2[2 * p + 1], ah, bl[2], bl[3]);
            mma16816(acc2[2 * p + 1], al, bh[2], bh[3]);
        }
    }

    const int nodeA = node0 + w * 16 + g;
    const int nodeB = nodeA + 8;
    #pragma unroll
    for (int nt = 0; nt < 8; nt++) {
        int col = nt * 8 + 2 * t;
        float bb0 = __ldg(&b2[col]);
        float bb1 = __ldg(&b2[col + 1]);
        if (nodeA < N) {
            const float2 xv = *(const float2*)&x[(size_t)nodeA * 64 + col];
            float2 o;
            o.x = xv.x + fmaxf(acc2[nt][0] + bb0, 0.f);
            o.y = xv.y + fmaxf(acc2[nt][1] + bb1, 0.f);
            *(float2*)&out[(size_t)nodeA * 64 + col] = o;
        }
        if (nodeB < N) {
            const float2 xv = *(const float2*)&x[(size_t)nodeB * 64 + col];
            float2 o;
            o.x = xv.x + fmaxf(acc2[nt][2] + bb0, 0.f);
            o.y = xv.y + fmaxf(acc2[nt][3] + bb1, 0.f);
            *(float2*)&out[(size_t)nodeB * 64 + col] = o;
        }
    }
}

// ===========================================================================
// Launch (5 kernels)
// ===========================================================================
extern "C" void kernel_launch(void* const* d_in, const int* in_sizes, int n_in,
                              void* d_out, int out_size) {
    const float* x   = (const float*)d_in[0];
    const int*   ei  = (const int*)d_in[1];
    const float* W1  = (const float*)d_in[2];
    const float* b1  = (const float*)d_in[3];
    const float* W2  = (const float*)d_in[4];
    const float* b2  = (const float*)d_in[5];
    float* out = (float*)d_out;

    int N = in_sizes[0] / DIM;       // 100000
    int E = in_sizes[1] / 2;         // 1600000
    const int* src = ei;
    const int* dst = ei + E;

    int nb = (N + 1023) / 1024;

    zero_count_kernel<<<(N + 255) / 256, 256>>>(N);
    hist_rank_kernel<<<(E + 255) / 256, 256>>>(dst, E);
    scan_kernel<<<nb, 1024>>>(N);
    fill_kernel<<<(E + 255) / 256, 256>>>(src, dst, E);

    static bool smem_set = false;
    if (!smem_set) {
        cudaFuncSetAttribute(fused_kernel,
                             cudaFuncAttributeMaxDynamicSharedMemorySize,
                             MLP_SMEM);
        smem_set = true;
    }
    fused_kernel<<<(N + 127) / 128, 256, MLP_SMEM>>>(x, W1, b1, W2, b2, out, N);
}

// round 12
// speedup vs baseline: 1.5188x; 1.5188x over previous
#include <cuda_runtime.h>
#include <cuda_bf16.h>
#include <cstdint>
#include <cstring>

#define DIM 64
#define NODES_MAX 100000
#define EDGES_MAX 1600000

// Allocation-free scratch (__device__ globals).
__device__ int            g_count[NODES_MAX];   // node degree (persists)
__device__ int            g_start[NODES_MAX];   // CSR bucket starts
__device__ int            g_csr[EDGES_MAX];     // src per bucketed edge
__device__ unsigned short g_rank[EDGES_MAX];    // edge rank within bucket
__device__ int            g_cursor;             // global bucket allocator
__device__ float          g_agg[(size_t)NODES_MAX * DIM];  // h = x + sum
__device__ uint4          g_wbuf[2304];         // 36864B split-bf16 weights

#define STRIDE 144
#define A_HI_OFF 0
#define A_LO_OFF 18432
#define B1H_OFF  36864
#define B1L_OFF  46080
#define B2H_OFF  55296
#define B2L_OFF  64512
#define MLP_SMEM 73728

__device__ __forceinline__ uint32_t pack_bf(__nv_bfloat16 a, __nv_bfloat16 b) {
    __nv_bfloat162 t;
    t.x = a; t.y = b;
    uint32_t r;
    memcpy(&r, &t, 4);
    return r;
}

__device__ __forceinline__ void split2(float a, float b,
                                       uint32_t& hi, uint32_t& lo) {
    __nv_bfloat16 ah = __float2bfloat16_rn(a);
    __nv_bfloat16 bh = __float2bfloat16_rn(b);
    hi = pack_bf(ah, bh);
    lo = pack_bf(__float2bfloat16_rn(a - __bfloat162float(ah)),
                 __float2bfloat16_rn(b - __bfloat162float(bh)));
}

// ===========================================================================
// 0. precompute split-bf16 weights in ldmatrix layout (4 blocks x 64 thr).
// Region p (0=B1H,1=B1L,2=B2H,3=B2L) is 64 rows x 144B; row n holds
// W^T[n][k] for k=0..63 (2B each).
// ===========================================================================
__global__ __launch_bounds__(64) void prep_weights_kernel(
        const float* __restrict__ W1, const float* __restrict__ W2) {
    const int part = blockIdx.x;        // 0..3
    const int n    = threadIdx.x;       // 0..63
    const float* W = (part < 2) ? W1 : W2;
    const bool lo  = part & 1;
    char* dst = (char*)g_wbuf + part * 9216 + n * STRIDE;
    #pragma unroll
    for (int q = 0; q < 8; q++) {
        uint32_t words[4];
        #pragma unroll
        for (int p = 0; p < 4; p++) {
            float v0 = __ldg(&W[(q * 8 + p * 2) * 64 + n]);
            float v1 = __ldg(&W[(q * 8 + p * 2 + 1) * 64 + n]);
            uint32_t hi, lw;
            split2(v0, v1, hi, lw);
            words[p] = lo ? lw : hi;
        }
        ((uint4*)dst)[q] = make_uint4(words[0], words[1], words[2], words[3]);
    }
}

// ===========================================================================
// 1. zero degree counters + global cursor
// ===========================================================================
__global__ void zero_count_kernel(int N) {
    int i = blockIdx.x * blockDim.x + threadIdx.x;
    if (i < N) g_count[i] = 0;
    if (i == 0) g_cursor = 0;
}

// ===========================================================================
// 2. histogram of dst; returned old value IS the edge's bucket rank (u16)
// ===========================================================================
__global__ void hist_rank_kernel(const int* __restrict__ dst, int E) {
    int i = blockIdx.x * blockDim.x + threadIdx.x;
    if (i < E) g_rank[i] = (unsigned short)atomicAdd(&g_count[dst[i]], 1);
}

// ===========================================================================
// 3. one-pass scan (warp-shuffle): per-block exclusive scan + atomic base.
// ===========================================================================
__global__ __launch_bounds__(1024) void scan_kernel(int N) {
    __shared__ int wsum[32];
    __shared__ int base_sh;
    const int t    = threadIdx.x;
    const int lane = t & 31;
    const int wid  = t >> 5;
    const int i    = blockIdx.x * 1024 + t;
    const int v    = (i < N) ? g_count[i] : 0;

    int s = v;   // inclusive warp scan
    #pragma unroll
    for (int off = 1; off < 32; off <<= 1) {
        int u = __shfl_up_sync(0xffffffffu, s, off);
        if (lane >= off) s += u;
    }
    if (lane == 31) wsum[wid] = s;
    __syncthreads();
    if (wid == 0) {
        int ws = wsum[lane];
        #pragma unroll
        for (int off = 1; off < 32; off <<= 1) {
            int u = __shfl_up_sync(0xffffffffu, ws, off);
            if (lane >= off) ws += u;
        }
        wsum[lane] = ws;
        if (lane == 31) base_sh = atomicAdd(&g_cursor, ws);
    }
    __syncthreads();
    int woff = (wid == 0) ? 0 : wsum[wid - 1];
    if (i < N) g_start[i] = base_sh + woff + s - v;
}

// ===========================================================================
// 4. atomic-free fill: pos = start[dst] + rank
// ===========================================================================
__global__ void fill_kernel(const int* __restrict__ src,
                            const int* __restrict__ dst, int E) {
    int i = blockIdx.x * blockDim.x + threadIdx.x;
    if (i < E) {
        g_csr[g_start[dst[i]] + (int)g_rank[i]] = src[i];
    }
}

// ===========================================================================
// 5. pull-gather: one warp per node (16 lanes x 2 slots, 4 loads in flight)
// ===========================================================================
__global__ __launch_bounds__(256) void gather_kernel(const float* __restrict__ x,
                                                     int N) {
    int warp = (blockIdx.x * blockDim.x + threadIdx.x) >> 5;
    if (warp >= N) return;
    const int lane = threadIdx.x & 31;
    const int c    = lane & 15;
    const int slot = lane >> 4;

    const float4* x4 = (const float4*)x;
    const int n = warp;
    const int s = g_start[n];
    const int e = s + g_count[n];

    float4 a = make_float4(0.f, 0.f, 0.f, 0.f);
    int j = s + slot;
    for (; j + 2 < e; j += 4) {
        int nb0 = __ldg(&g_csr[j]);
        int nb1 = __ldg(&g_csr[j + 2]);
        float4 v0 = __ldg(&x4[(size_t)nb0 * 16 + c]);
        float4 v1 = __ldg(&x4[(size_t)nb1 * 16 + c]);
        a.x += v0.x + v1.x;
        a.y += v0.y + v1.y;
        a.z += v0.z + v1.z;
        a.w += v0.w + v1.w;
    }
    if (j < e) {
        int nb = __ldg(&g_csr[j]);
        float4 v = __ldg(&x4[(size_t)nb * 16 + c]);
        a.x += v.x; a.y += v.y; a.z += v.z; a.w += v.w;
    }

    a.x += __shfl_xor_sync(0xffffffffu, a.x, 16);
    a.y += __shfl_xor_sync(0xffffffffu, a.y, 16);
    a.z += __shfl_xor_sync(0xffffffffu, a.z, 16);
    a.w += __shfl_xor_sync(0xffffffffu, a.w, 16);

    if (slot == 0) {
        float4 xv = x4[(size_t)n * 16 + c];
        ((float4*)g_agg)[(size_t)n * 16 + c] =
            make_float4(xv.x + a.x, xv.y + a.y, xv.z + a.z, xv.w + a.w);
    }
}

// ===========================================================================
// 6. Tensor-core MLP (mma.sync m16n8k16 bf16, split precision).
// Weights copied pre-split from g_wbuf (36KB float4 copy, L2 broadcast).
// ===========================================================================
__device__ __forceinline__ uint32_t smem_u32(const void* p) {
    uint32_t a;
    asm("{ .reg .u64 t; cvta.to.shared.u64 t, %1; cvt.u32.u64 %0, t; }"
        : "=r"(a) : "l"(p));
    return a;
}

__device__ __forceinline__ void ldm4(uint32_t* f, uint32_t addr) {
    asm volatile("ldmatrix.sync.aligned.m8n8.x4.shared.b16 {%0,%1,%2,%3}, [%4];"
                 : "=r"(f[0]), "=r"(f[1]), "=r"(f[2]), "=r"(f[3]) : "r"(addr));
}

__device__ __forceinline__ void mma16816(float* d, const uint32_t* a,
                                         uint32_t b0, uint32_t b1) {
    asm volatile(
        "mma.sync.aligned.m16n8k16.row.col.f32.bf16.bf16.f32 "
        "{%0,%1,%2,%3}, {%4,%5,%6,%7}, {%8,%9}, {%0,%1,%2,%3};"
        : "+f"(d[0]), "+f"(d[1]), "+f"(d[2]), "+f"(d[3])
        : "r"(a[0]), "r"(a[1]), "r"(a[2]), "r"(a[3]), "r"(b0), "r"(b1));
}

__global__ __launch_bounds__(256) void mlp_tc_kernel(const float* __restrict__ x,
                                                     const float* __restrict__ b1,
                                                     const float* __restrict__ b2,
                                                     float* __restrict__ out,
                                                     int N) {
    extern __shared__ char sm[];
    const uint32_t sbase = smem_u32(sm);
    const int tid  = threadIdx.x;
    const int node0 = blockIdx.x * 128;

    // ---- stage A: split-bf16 h tile from g_agg ----
    for (int i = tid; i < 2048; i += 256) {
        int m  = i >> 4;
        int f4 = i & 15;
        int node = node0 + m;
        float4 v = (node < N) ? ((const float4*)g_agg)[(size_t)node * 16 + f4]
                              : make_float4(0.f, 0.f, 0.f, 0.f);
        uint32_t h0, l0, h1, l1;
        split2(v.x, v.y, h0, l0);
        split2(v.z, v.w, h1, l1);
        uint32_t off = (uint32_t)m * STRIDE + (uint32_t)f4 * 8;
        *(uint2*)(sm + A_HI_OFF + off) = make_uint2(h0, h1);
        *(uint2*)(sm + A_LO_OFF + off) = make_uint2(l0, l1);
    }

    // ---- stage B: copy pre-split weights (2304 uint4) ----
    for (int i = tid; i < 2304; i += 256) {
        ((uint4*)(sm + B1H_OFF))[i] = g_wbuf[i];
    }
    __syncthreads();

    const int w    = tid >> 5;
    const int lane = tid & 31;
    const int g    = lane >> 2;
    const int t    = lane & 3;
    const int q    = lane >> 3;
    const int r    = lane & 7;

    const uint32_t aoff = (uint32_t)(w * 16 + (q & 1) * 8 + r) * STRIDE
                        + (uint32_t)(q >> 1) * 16;
    const uint32_t boff0 = (uint32_t)((q >> 1) * 8 + r) * STRIDE
                         + (uint32_t)(q & 1) * 16;

    float acc1[8][4];
    #pragma unroll
    for (int n = 0; n < 8; n++)
        #pragma unroll
        for (int j = 0; j < 4; j++) acc1[n][j] = 0.f;

    #pragma unroll
    for (int kk = 0; kk < 4; kk++) {
        uint32_t ah[4], al[4];
        ldm4(ah, sbase + A_HI_OFF + aoff + kk * 32);
        ldm4(al, sbase + A_LO_OFF + aoff + kk * 32);
        #pragma unroll
        for (int p = 0; p < 4; p++) {
            uint32_t bo = boff0 + (uint32_t)p * 16 * STRIDE + kk * 32;
            uint32_t bh[4], bl[4];
            ldm4(bh, sbase + B1H_OFF + bo);
            ldm4(bl, sbase + B1L_OFF + bo);
            mma16816(acc1[2 * p],     ah, bh[0], bh[1]);
            mma16816(acc1[2 * p],     ah, bl[0], bl[1]);
            mma16816(acc1[2 * p],     al, bh[0], bh[1]);
            mma16816(acc1[2 * p + 1], ah, bh[2], bh[3]);
            mma16816(acc1[2 * p + 1], ah, bl[2], bl[3]);
            mma16816(acc1[2 * p + 1], al, bh[2], bh[3]);
        }
    }

    float acc2[8][4];
    #pragma unroll
    for (int n = 0; n < 8; n++)
        #pragma unroll
        for (int j = 0; j < 4; j++) acc2[n][j] = 0.f;

    #pragma unroll
    for (int kk = 0; kk < 4; kk++) {
        uint32_t ah[4], al[4];
        {
            int nt = 2 * kk;
            float bb0 = __ldg(&b1[nt * 8 + 2 * t]);
            float bb1 = __ldg(&b1[nt * 8 + 2 * t + 1]);
            split2(fmaxf(acc1[nt][0] + bb0, 0.f),
                   fmaxf(acc1[nt][1] + bb1, 0.f), ah[0], al[0]);
            split2(fmaxf(acc1[nt][2] + bb0, 0.f),
                   fmaxf(acc1[nt][3] + bb1, 0.f), ah[1], al[1]);
            nt = 2 * kk + 1;
            bb0 = __ldg(&b1[nt * 8 + 2 * t]);
            bb1 = __ldg(&b1[nt * 8 + 2 * t + 1]);
            split2(fmaxf(acc1[nt][0] + bb0, 0.f),
                   fmaxf(acc1[nt][1] + bb1, 0.f), ah[2], al[2]);
            split2(fmaxf(acc1[nt][2] + bb0, 0.f),
                   fmaxf(acc1[nt][3] + bb1, 0.f), ah[3], al[3]);
        }
        #pragma unroll
        for (int p = 0; p < 4; p++) {
            uint32_t bo = boff0 + (uint32_t)p * 16 * STRIDE + kk * 32;
            uint32_t bh[4], bl[4];
            ldm4(bh, sbase + B2H_OFF + bo);
            ldm4(bl, sbase + B2L_OFF + bo);
            mma16816(acc2[2 * p],     ah, bh[0], bh[1]);
            mma16816(acc2[2 * p],     ah, bl[0], bl[1]);
            mma16816(acc2[2 * p],     al, bh[0], bh[1]);
            mma16816(acc2[2 * p + 1], ah, bh[2], bh[3]);
            mma16816(acc2[2 * p + 1], ah, bl[2], bl[3]);
            mma16816(acc2[2 * p + 1], al, bh[2], bh[3]);
        }
    }

    const int nodeA = node0 + w * 16 + g;
    const int nodeB = nodeA + 8;
    #pragma unroll
    for (int nt = 0; nt < 8; nt++) {
        int col = nt * 8 + 2 * t;
        float bb0 = __ldg(&b2[col]);
        float bb1 = __ldg(&b2[col + 1]);
        if (nodeA < N) {
            const float2 xv = *(const float2*)&x[(size_t)nodeA * 64 + col];
            float2 o;
            o.x = xv.x + fmaxf(acc2[nt][0] + bb0, 0.f);
            o.y = xv.y + fmaxf(acc2[nt][1] + bb1, 0.f);
            *(float2*)&out[(size_t)nodeA * 64 + col] = o;
        }
        if (nodeB < N) {
            const float2 xv = *(const float2*)&x[(size_t)nodeB * 64 + col];
            float2 o;
            o.x = xv.x + fmaxf(acc2[nt][2] + bb0, 0.f);
            o.y = xv.y + fmaxf(acc2[nt][3] + bb1, 0.f);
            *(float2*)&out[(size_t)nodeB * 64 + col] = o;
        }
    }
}

// ===========================================================================
// Launch (6 kernels; prep_weights is tiny)
// ===========================================================================
extern "C" void kernel_launch(void* const* d_in, const int* in_sizes, int n_in,
                              void* d_out, int out_size) {
    const float* x   = (const float*)d_in[0];
    const int*   ei  = (const int*)d_in[1];
    const float* W1  = (const float*)d_in[2];
    const float* b1  = (const float*)d_in[3];
    const float* W2  = (const float*)d_in[4];
    const float* b2  = (const float*)d_in[5];
    float* out = (float*)d_out;

    int N = in_sizes[0] / DIM;       // 100000
    int E = in_sizes[1] / 2;         // 1600000
    const int* src = ei;
    const int* dst = ei + E;

    int nb = (N + 1023) / 1024;

    prep_weights_kernel<<<4, 64>>>(W1, W2);
    zero_count_kernel<<<(N + 255) / 256, 256>>>(N);
    hist_rank_kernel<<<(E + 255) / 256, 256>>>(dst, E);
    scan_kernel<<<nb, 1024>>>(N);
    fill_kernel<<<(E + 255) / 256, 256>>>(src, dst, E);
    gather_kernel<<<(N * 32 + 255) / 256, 256>>>(x, N);

    static bool smem_set = false;
    if (!smem_set) {
        cudaFuncSetAttribute(mlp_tc_kernel,
                             cudaFuncAttributeMaxDynamicSharedMemorySize,
                             MLP_SMEM);
        smem_set = true;
    }
    mlp_tc_kernel<<<(N + 127) / 128, 256, MLP_SMEM>>>(x, b1, b2, out, N);
}

// round 13
// speedup vs baseline: 1.5772x; 1.0385x over previous
#include <cuda_runtime.h>
#include <cuda_bf16.h>
#include <cstdint>
#include <cstring>

#define DIM 64
#define NODES_MAX 100000
#define EDGES_MAX 1600000

// Allocation-free scratch (__device__ globals; zero-initialized at load).
// SELF-CLEANING INVARIANT: g_count and g_cursor are zero at the start of
// every kernel_launch invocation. gather re-zeroes g_count after consuming
// it; fill re-zeroes g_cursor after scan consumed it.
__device__ int            g_count[NODES_MAX];   // degree accumulator
__device__ int            g_start[NODES_MAX];   // CSR bucket starts (fill)
__device__ int2           g_sc[NODES_MAX];      // {start, count} (gather)
__device__ int            g_csr[EDGES_MAX];     // src per bucketed edge
__device__ unsigned short g_rank[EDGES_MAX];    // edge rank within bucket
__device__ int            g_cursor;             // global bucket allocator
__device__ float          g_agg[(size_t)NODES_MAX * DIM];  // h = x + sum
__device__ uint4          g_wbuf[2304];         // 36864B split-bf16 weights

#define STRIDE 144
#define A_HI_OFF 0
#define A_LO_OFF 18432
#define B1H_OFF  36864
#define B1L_OFF  46080
#define B2H_OFF  55296
#define B2L_OFF  64512
#define MLP_SMEM 73728

__device__ __forceinline__ uint32_t pack_bf(__nv_bfloat16 a, __nv_bfloat16 b) {
    __nv_bfloat162 t;
    t.x = a; t.y = b;
    uint32_t r;
    memcpy(&r, &t, 4);
    return r;
}

__device__ __forceinline__ void split2(float a, float b,
                                       uint32_t& hi, uint32_t& lo) {
    __nv_bfloat16 ah = __float2bfloat16_rn(a);
    __nv_bfloat16 bh = __float2bfloat16_rn(b);
    hi = pack_bf(ah, bh);
    lo = pack_bf(__float2bfloat16_rn(a - __bfloat162float(ah)),
                 __float2bfloat16_rn(b - __bfloat162float(bh)));
}

// ===========================================================================
// 1. histogram of dst (rank = returned old count) + weight prep in 4 extra
// blocks (blockIdx >= EB). g_count starts zero (invariant above).
// ===========================================================================
__global__ __launch_bounds__(256) void hist_prep_kernel(
        const int* __restrict__ dst, int E, int EB,
        const float* __restrict__ W1, const float* __restrict__ W2) {
    if (blockIdx.x >= EB) {
        // split-bf16 weight image, ldmatrix layout:
        // part 0=B1H,1=B1L,2=B2H,3=B2L; row n = W^T[n][k], k=0..63
        const int part = blockIdx.x - EB;        // 0..3
        const int n    = threadIdx.x;
        if (n < 64) {
            const float* W = (part < 2) ? W1 : W2;
            const bool lo  = part & 1;
            char* dstp = (char*)g_wbuf + part * 9216 + n * STRIDE;
            #pragma unroll
            for (int q = 0; q < 8; q++) {
                uint32_t words[4];
                #pragma unroll
                for (int p = 0; p < 4; p++) {
                    float v0 = __ldg(&W[(q * 8 + p * 2) * 64 + n]);
                    float v1 = __ldg(&W[(q * 8 + p * 2 + 1) * 64 + n]);
                    uint32_t hi, lw;
                    split2(v0, v1, hi, lw);
                    words[p] = lo ? lw : hi;
                }
                ((uint4*)dstp)[q] =
                    make_uint4(words[0], words[1], words[2], words[3]);
            }
        }
        return;
    }
    int i = blockIdx.x * 256 + threadIdx.x;
    if (i < E) g_rank[i] = (unsigned short)atomicAdd(&g_count[dst[i]], 1);
}

// ===========================================================================
// 2. one-pass scan (warp-shuffle): per-block exclusive scan + atomic base.
// Writes g_start (for fill) and packed g_sc = {start, count} (for gather).
// ===========================================================================
__global__ __launch_bounds__(1024) void scan_kernel(int N) {
    __shared__ int wsum[32];
    __shared__ int base_sh;
    const int t    = threadIdx.x;
    const int lane = t & 31;
    const int wid  = t >> 5;
    const int i    = blockIdx.x * 1024 + t;
    const int v    = (i < N) ? g_count[i] : 0;

    int s = v;   // inclusive warp scan
    #pragma unroll
    for (int off = 1; off < 32; off <<= 1) {
        int u = __shfl_up_sync(0xffffffffu, s, off);
        if (lane >= off) s += u;
    }
    if (lane == 31) wsum[wid] = s;
    __syncthreads();
    if (wid == 0) {
        int ws = wsum[lane];
        #pragma unroll
        for (int off = 1; off < 32; off <<= 1) {
            int u = __shfl_up_sync(0xffffffffu, ws, off);
            if (lane >= off) ws += u;
        }
        wsum[lane] = ws;
        if (lane == 31) base_sh = atomicAdd(&g_cursor, ws);
    }
    __syncthreads();
    int woff = (wid == 0) ? 0 : wsum[wid - 1];
    if (i < N) {
        int st = base_sh + woff + s - v;
        g_start[i] = st;
        g_sc[i] = make_int2(st, v);
    }
}

// ===========================================================================
// 3. atomic-free fill: pos = start[dst] + rank. Also resets g_cursor
// (scan, its only reader, has completed).
// ===========================================================================
__global__ __launch_bounds__(256) void fill_kernel(const int* __restrict__ src,
                                                   const int* __restrict__ dst,
                                                   int E) {
    int i = blockIdx.x * 256 + threadIdx.x;
    if (i == 0) g_cursor = 0;
    if (i < E) {
        g_csr[g_start[dst[i]] + (int)g_rank[i]] = src[i];
    }
}

// ===========================================================================
// 4. pull-gather: one warp per node (16 lanes x 2 slots, 4 loads in flight).
// Reads packed {start,count}; re-zeroes g_count for the next invocation.
// ===========================================================================
__global__ __launch_bounds__(256) void gather_kernel(const float* __restrict__ x,
                                                     int N) {
    int warp = (blockIdx.x * blockDim.x + threadIdx.x) >> 5;
    if (warp >= N) return;
    const int lane = threadIdx.x & 31;
    const int c    = lane & 15;
    const int slot = lane >> 4;

    const float4* x4 = (const float4*)x;
    const int n = warp;
    const int2 sc = __ldg(&g_sc[n]);
    const int s = sc.x;
    const int e = s + sc.y;

    if (lane == 0) g_count[n] = 0;   // restore zero invariant

    float4 a = make_float4(0.f, 0.f, 0.f, 0.f);
    int j = s + slot;
    for (; j + 2 < e; j += 4) {
        int nb0 = __ldg(&g_csr[j]);
        int nb1 = __ldg(&g_csr[j + 2]);
        float4 v0 = __ldg(&x4[(size_t)nb0 * 16 + c]);
        float4 v1 = __ldg(&x4[(size_t)nb1 * 16 + c]);
        a.x += v0.x + v1.x;
        a.y += v0.y + v1.y;
        a.z += v0.z + v1.z;
        a.w += v0.w + v1.w;
    }
    if (j < e) {
        int nb = __ldg(&g_csr[j]);
        float4 v = __ldg(&x4[(size_t)nb * 16 + c]);
        a.x += v.x; a.y += v.y; a.z += v.z; a.w += v.w;
    }

    a.x += __shfl_xor_sync(0xffffffffu, a.x, 16);
    a.y += __shfl_xor_sync(0xffffffffu, a.y, 16);
    a.z += __shfl_xor_sync(0xffffffffu, a.z, 16);
    a.w += __shfl_xor_sync(0xffffffffu, a.w, 16);

    if (slot == 0) {
        float4 xv = x4[(size_t)n * 16 + c];
        ((float4*)g_agg)[(size_t)n * 16 + c] =
            make_float4(xv.x + a.x, xv.y + a.y, xv.z + a.z, xv.w + a.w);
    }
}

// ===========================================================================
// 5. Tensor-core MLP (mma.sync m16n8k16 bf16, split precision).
// ===========================================================================
__device__ __forceinline__ uint32_t smem_u32(const void* p) {
    uint32_t a;
    asm("{ .reg .u64 t; cvta.to.shared.u64 t, %1; cvt.u32.u64 %0, t; }"
        : "=r"(a) : "l"(p));
    return a;
}

__device__ __forceinline__ void ldm4(uint32_t* f, uint32_t addr) {
    asm volatile("ldmatrix.sync.aligned.m8n8.x4.shared.b16 {%0,%1,%2,%3}, [%4];"
                 : "=r"(f[0]), "=r"(f[1]), "=r"(f[2]), "=r"(f[3]) : "r"(addr));
}

__device__ __forceinline__ void mma16816(float* d, const uint32_t* a,
                                         uint32_t b0, uint32_t b1) {
    asm volatile(
        "mma.sync.aligned.m16n8k16.row.col.f32.bf16.bf16.f32 "
        "{%0,%1,%2,%3}, {%4,%5,%6,%7}, {%8,%9}, {%0,%1,%2,%3};"
        : "+f"(d[0]), "+f"(d[1]), "+f"(d[2]), "+f"(d[3])
        : "r"(a[0]), "r"(a[1]), "r"(a[2]), "r"(a[3]), "r"(b0), "r"(b1));
}

__global__ __launch_bounds__(256) void mlp_tc_kernel(const float* __restrict__ x,
                                                     const float* __restrict__ b1,
                                                     const float* __restrict__ b2,
                                                     float* __restrict__ out,
                                                     int N) {
    extern __shared__ char sm[];
    const uint32_t sbase = smem_u32(sm);
    const int tid  = threadIdx.x;
    const int node0 = blockIdx.x * 128;

    // stage A: split-bf16 h tile from g_agg
    for (int i = tid; i < 2048; i += 256) {
        int m  = i >> 4;
        int f4 = i & 15;
        int node = node0 + m;
        float4 v = (node < N) ? ((const float4*)g_agg)[(size_t)node * 16 + f4]
                              : make_float4(0.f, 0.f, 0.f, 0.f);
        uint32_t h0, l0, h1, l1;
        split2(v.x, v.y, h0, l0);
        split2(v.z, v.w, h1, l1);
        uint32_t off = (uint32_t)m * STRIDE + (uint32_t)f4 * 8;
        *(uint2*)(sm + A_HI_OFF + off) = make_uint2(h0, h1);
        *(uint2*)(sm + A_LO_OFF + off) = make_uint2(l0, l1);
    }

    // stage B: copy pre-split weights (2304 uint4, L2 broadcast)
    for (int i = tid; i < 2304; i += 256) {
        ((uint4*)(sm + B1H_OFF))[i] = g_wbuf[i];
    }
    __syncthreads();

    const int w    = tid >> 5;
    const int lane = tid & 31;
    const int g    = lane >> 2;
    const int t    = lane & 3;
    const int q    = lane >> 3;
    const int r    = lane & 7;

    const uint32_t aoff = (uint32_t)(w * 16 + (q & 1) * 8 + r) * STRIDE
                        + (uint32_t)(q >> 1) * 16;
    const uint32_t boff0 = (uint32_t)((q >> 1) * 8 + r) * STRIDE
                         + (uint32_t)(q & 1) * 16;

    float acc1[8][4];
    #pragma unroll
    for (int n = 0; n < 8; n++)
        #pragma unroll
        for (int j = 0; j < 4; j++) acc1[n][j] = 0.f;

    #pragma unroll
    for (int kk = 0; kk < 4; kk++) {
        uint32_t ah[4], al[4];
        ldm4(ah, sbase + A_HI_OFF + aoff + kk * 32);
        ldm4(al, sbase + A_LO_OFF + aoff + kk * 32);
        #pragma unroll
        for (int p = 0; p < 4; p++) {
            uint32_t bo = boff0 + (uint32_t)p * 16 * STRIDE + kk * 32;
            uint32_t bh[4], bl[4];
            ldm4(bh, sbase + B1H_OFF + bo);
            ldm4(bl, sbase + B1L_OFF + bo);
            mma16816(acc1[2 * p],     ah, bh[0], bh[1]);
            mma16816(acc1[2 * p],     ah, bl[0], bl[1]);
            mma16816(acc1[2 * p],     al, bh[0], bh[1]);
            mma16816(acc1[2 * p + 1], ah, bh[2], bh[3]);
            mma16816(acc1[2 * p + 1], ah, bl[2], bl[3]);
            mma16816(acc1[2 * p + 1], al, bh[2], bh[3]);
        }
    }

    float acc2[8][4];
    #pragma unroll
    for (int n = 0; n < 8; n++)
        #pragma unroll
        for (int j = 0; j < 4; j++) acc2[n][j] = 0.f;

    #pragma unroll
    for (int kk = 0; kk < 4; kk++) {
        uint32_t ah[4], al[4];
        {
            int nt = 2 * kk;
            float bb0 = __ldg(&b1[nt * 8 + 2 * t]);
            float bb1 = __ldg(&b1[nt * 8 + 2 * t + 1]);
            split2(fmaxf(acc1[nt][0] + bb0, 0.f),
                   fmaxf(acc1[nt][1] + bb1, 0.f), ah[0], al[0]);
            split2(fmaxf(acc1[nt][2] + bb0, 0.f),
                   fmaxf(acc1[nt][3] + bb1, 0.f), ah[1], al[1]);
            nt = 2 * kk + 1;
            bb0 = __ldg(&b1[nt * 8 + 2 * t]);
            bb1 = __ldg(&b1[nt * 8 + 2 * t + 1]);
            split2(fmaxf(acc1[nt][0] + bb0, 0.f),
                   fmaxf(acc1[nt][1] + bb1, 0.f), ah[2], al[2]);
            split2(fmaxf(acc1[nt][2] + bb0, 0.f),
                   fmaxf(acc1[nt][3] + bb1, 0.f), ah[3], al[3]);
        }
        #pragma unroll
        for (int p = 0; p < 4; p++) {
            uint32_t bo = boff0 + (uint32_t)p * 16 * STRIDE + kk * 32;
            uint32_t bh[4], bl[4];
            ldm4(bh, sbase + B2H_OFF + bo);
            ldm4(bl, sbase + B2L_OFF + bo);
            mma16816(acc2[2 * p],     ah, bh[0], bh[1]);
            mma16816(acc2[2 * p],     ah, bl[0], bl[1]);
            mma16816(acc2[2 * p],     al, bh[0], bh[1]);
            mma16816(acc2[2 * p + 1], ah, bh[2], bh[3]);
            mma16816(acc2[2 * p + 1], ah, bl[2], bl[3]);
            mma16816(acc2[2 * p + 1], al, bh[2], bh[3]);
        }
    }

    const int nodeA = node0 + w * 16 + g;
    const int nodeB = nodeA + 8;
    #pragma unroll
    for (int nt = 0; nt < 8; nt++) {
        int col = nt * 8 + 2 * t;
        float bb0 = __ldg(&b2[col]);
        float bb1 = __ldg(&b2[col + 1]);
        if (nodeA < N) {
            const float2 xv = *(const float2*)&x[(size_t)nodeA * 64 + col];
            float2 o;
            o.x = xv.x + fmaxf(acc2[nt][0] + bb0, 0.f);
            o.y = xv.y + fmaxf(acc2[nt][1] + bb1, 0.f);
            *(float2*)&out[(size_t)nodeA * 64 + col] = o;
        }
        if (nodeB < N) {
            const float2 xv = *(const float2*)&x[(size_t)nodeB * 64 + col];
            float2 o;
            o.x = xv.x + fmaxf(acc2[nt][2] + bb0, 0.f);
            o.y = xv.y + fmaxf(acc2[nt][3] + bb1, 0.f);
            *(float2*)&out[(size_t)nodeB * 64 + col] = o;
        }
    }
}

// ===========================================================================
// Launch (5 kernels)
// ===========================================================================
extern "C" void kernel_launch(void* const* d_in, const int* in_sizes, int n_in,
                              void* d_out, int out_size) {
    const float* x   = (const float*)d_in[0];
    const int*   ei  = (const int*)d_in[1];
    const float* W1  = (const float*)d_in[2];
    const float* b1  = (const float*)d_in[3];
    const float* W2  = (const float*)d_in[4];
    const float* b2  = (const float*)d_in[5];
    float* out = (float*)d_out;

    int N = in_sizes[0] / DIM;       // 100000
    int E = in_sizes[1] / 2;         // 1600000
    const int* src = ei;
    const int* dst = ei + E;

    int EB = (E + 255) / 256;
    int nb = (N + 1023) / 1024;

    hist_prep_kernel<<<EB + 4, 256>>>(dst, E, EB, W1, W2);
    scan_kernel<<<nb, 1024>>>(N);
    fill_kernel<<<EB, 256>>>(src, dst, E);
    gather_kernel<<<(N * 32 + 255) / 256, 256>>>(x, N);

    static bool smem_set = false;
    if (!smem_set) {
        cudaFuncSetAttribute(mlp_tc_kernel,
                             cudaFuncAttributeMaxDynamicSharedMemorySize,
                             MLP_SMEM);
        smem_set = true;
    }
    mlp_tc_kernel<<<(N + 127) / 128, 256, MLP_SMEM>>>(x, b1, b2, out, N);
}